// round 14
// baseline (speedup 1.0000x reference)
#include <cuda_runtime.h>
#include <cstdint>

#define N_NODES 20000
#define N_EDGES 1280000
#define IN_DIM 16
#define HID 128
#define G3 384
#define OUT_DIM 4

// ---------------- scratch (static device globals; no allocation) ----------------
__device__ float g_deg[N_NODES];
__device__ float g_s[N_NODES * HID];      // (x@W_gcn) * dinv  (messages, pre-scaled)
__device__ float g_agg[N_NODES * HID];    // scatter-add accumulator (init = self term)
__device__ float g_xg[N_NODES * G3];      // precomputed input gates
__device__ float g_ys[N_NODES * HID];     // GRU outputs

// ---------------- packed f32x2 helpers ----------------
__device__ __forceinline__ unsigned long long ffma2(unsigned long long a,
                                                    unsigned long long b,
                                                    unsigned long long c) {
    unsigned long long d;
    asm("fma.rn.f32x2 %0, %1, %2, %3;" : "=l"(d) : "l"(a), "l"(b), "l"(c));
    return d;
}
__device__ __forceinline__ unsigned long long addf2(unsigned long long a,
                                                    unsigned long long b) {
    unsigned long long d;
    asm("add.rn.f32x2 %0, %1, %2;" : "=l"(d) : "l"(a), "l"(b));
    return d;
}
__device__ __forceinline__ float2 u2f2(unsigned long long u) {
    float2 f;
    asm("mov.b64 {%0, %1}, %2;" : "=f"(f.x), "=f"(f.y) : "l"(u));
    return f;
}
__device__ __forceinline__ unsigned long long packf2(float lo, float hi) {
    unsigned long long u;
    asm("mov.b64 %0, {%1, %2};" : "=l"(u) : "f"(lo), "f"(hi));
    return u;
}
// MUFU.TANH-based activations (measured R8/R9: negligible accumulated error)
__device__ __forceinline__ float tanh_fast(float x) {
    float y;
    asm("tanh.approx.f32 %0, %1;" : "=f"(y) : "f"(x));
    return y;
}
__device__ __forceinline__ float sigmoid_fast_half(float half_x) {
    // sigmoid(x) = 0.5*tanh(x/2)+0.5, caller passes x/2
    return fmaf(tanh_fast(half_x), 0.5f, 0.5f);
}

// ---------------- K1: deg init (self-loop => 1) ----------------
__global__ void k_init_deg() {
    int i = blockIdx.x * blockDim.x + threadIdx.x;
    if (i < N_NODES) g_deg[i] = 1.0f;
}

// ---------------- K2: in-degree over targets ----------------
__global__ void k_deg(const int* __restrict__ ei) {
    int e = blockIdx.x * blockDim.x + threadIdx.x;
    if (e < N_EDGES) atomicAdd(&g_deg[ei[N_EDGES + e]], 1.0f);
}

// ---------------- K3: s = (x @ W_gcn) * dinv ; agg init with self term ----------------
__global__ void k_lin(const float* __restrict__ x, const float* __restrict__ Wg) {
    __shared__ float sx[IN_DIM];
    int node = blockIdx.x;
    int tid = threadIdx.x;  // 128 threads
    if (tid < IN_DIM) sx[tid] = x[node * IN_DIM + tid];
    __syncthreads();
    float acc = 0.0f;
#pragma unroll
    for (int k = 0; k < IN_DIM; k++) acc = fmaf(sx[k], Wg[k * HID + tid], acc);
    float s = acc * rsqrtf(g_deg[node]);
    g_s[(size_t)node * HID + tid] = s;
    g_agg[(size_t)node * HID + tid] = s;  // self-loop contribution (pre outer dinv)
}

// ---------------- K4: scatter-add messages (vector red.v4) ----------------
__global__ void k_scatter(const int* __restrict__ ei) {
    long long gid = (long long)blockIdx.x * blockDim.x + threadIdx.x;
    if (gid >= (long long)N_EDGES * (HID / 4)) return;
    int e = (int)(gid >> 5);          // 32 float4 chunks per edge
    int q = (int)(gid & 31);
    int r = ei[e];
    int c = ei[N_EDGES + e];
    const float4* src = (const float4*)(g_s + (size_t)r * HID) + q;
    float4 v = *src;
    float* dst = g_agg + (size_t)c * HID + 4 * q;
    asm volatile("red.global.v4.f32.add [%0], {%1, %2, %3, %4};"
                 :: "l"(dst), "f"(v.x), "f"(v.y), "f"(v.z), "f"(v.w) : "memory");
}

// ---------------- K5: xg = (agg*dinv + b_gcn) @ W_ih.T + b_ih ----------------
__global__ void __launch_bounds__(G3, 1)
k_xg(const float* __restrict__ Wih, const float* __restrict__ bih,
     const float* __restrict__ bgcn) {
    __shared__ __align__(16) float sg[HID];
    int tid = threadIdx.x;
    unsigned long long w[HID / 2];
    const unsigned long long* wr =
        (const unsigned long long*)(Wih + (size_t)tid * HID);
#pragma unroll
    for (int m = 0; m < HID / 2; m++) w[m] = wr[m];
    float b = bih[tid];
    float bg = (tid < HID) ? bgcn[tid] : 0.0f;

    for (int node = blockIdx.x; node < N_NODES; node += gridDim.x) {
        __syncthreads();
        if (tid < HID) {
            float dv = rsqrtf(g_deg[node]);
            sg[tid] = fmaf(g_agg[(size_t)node * HID + tid], dv, bg);
        }
        __syncthreads();
        unsigned long long a0 = 0ull, a1 = 0ull;
        const ulonglong2* hp = (const ulonglong2*)sg;
#pragma unroll
        for (int m = 0; m < HID / 4; m++) {   // 32 entries: full 128 floats
            ulonglong2 hv = hp[m];
            a0 = ffma2(w[2 * m], hv.x, a0);
            a1 = ffma2(w[2 * m + 1], hv.y, a1);
        }
        float2 f0 = u2f2(a0), f1 = u2f2(a1);
        g_xg[(size_t)node * G3 + tid] = f0.x + f0.y + f1.x + f1.y + b;
    }
}

// ---------------- K6: sequential GRU scan (single CTA, persistent) ----------------
// R9-green structure. Deltas (issue-count justified):
//   - g_ys STG rotated off the serial handoff: grp2 stores step t-1's h at the
//     top of step t (overlaps the dot), final value flushed after the loop.
//   - xg_own folded into the packed reduction (one fewer dependent FADD
//     before each gate's MUFU).
__global__ void __launch_bounds__(G3, 1)
k_gru(const float* __restrict__ Whh, const float* __restrict__ bhh,
      const float* __restrict__ h0, float* __restrict__ hT) {
    __shared__ __align__(16) float sh_h[HID];
    __shared__ float sh_r[HID];
    __shared__ float sh_z[HID];
    int tid = threadIdx.x;
    int grp = tid >> 7;  // 0,1,2
    int j = tid & 127;

    unsigned long long w[HID / 2];  // 64 ull = 128 regs
    const unsigned long long* wr =
        (const unsigned long long*)(Whh + (size_t)tid * HID);
#pragma unroll
    for (int m = 0; m < HID / 2; m++) w[m] = wr[m];
    float bh = bhh[tid];

    if (tid < HID) sh_h[tid] = h0[tid];
    float xg_cur = g_xg[tid];  // t = 0 prefetch
    float ys_pending = 0.0f;   // grp2: h(t-1) awaiting deferred store
    __syncthreads();

    for (int t = 0; t < N_NODES; t++) {
        // deferred g_ys store for step t-1 (grp2 only; overlaps the dot)
        if (grp == 2 && t > 0) g_ys[(size_t)(t - 1) * HID + j] = ys_pending;

        const ulonglong2* hp = (const ulonglong2*)sh_h;  // 32 entries (4 floats)

        // ---- dot: hg-sum with bias AND xg folded into the packed tree ----
        unsigned long long a0 = packf2(bh, 0.0f), a1 = 0ull, a2 = 0ull, a3 = 0ull;
#pragma unroll
        for (int m = 0; m < HID / 8; m++) {   // 16 iters over hp[0..31], w[0..63]
            ulonglong2 u = hp[2 * m];
            ulonglong2 v = hp[2 * m + 1];
            a0 = ffma2(w[4 * m + 0], u.x, a0);
            a1 = ffma2(w[4 * m + 1], u.y, a1);
            a2 = ffma2(w[4 * m + 2], v.x, a2);
            a3 = ffma2(w[4 * m + 3], v.y, a3);
        }
        float xg_own = xg_cur;
        int tn = (t + 1 < N_NODES) ? (t + 1) : (N_NODES - 1);  // branch-free clamp
        xg_cur = g_xg[(size_t)tn * G3 + tid];

        // hg (without xg) needed only by grp2's n-gate (r*hn term); for the
        // sigmoids we need xg+hg, folded here:
        unsigned long long sA = addf2(addf2(a0, a1), addf2(a2, a3));
        float2 fs = u2f2(sA);
        float hg = fs.x + fs.y;            // = W.h + b
        float g_sum = hg + xg_own;         // = xg + W.h + b

        if (grp == 0) {
            sh_r[j] = sigmoid_fast_half(0.5f * g_sum);
            asm volatile("bar.arrive 1, %0;" :: "n"(G3) : "memory");
        } else if (grp == 1) {
            sh_z[j] = sigmoid_fast_half(0.5f * g_sum);
            asm volatile("bar.arrive 1, %0;" :: "n"(G3) : "memory");
        } else {
            float h_old = sh_h[j];  // own-thread slot, stable until we write it
            asm volatile("bar.sync 1, %0;" :: "n"(G3) : "memory");
            float r = sh_r[j];
            float z = sh_z[j];
            float narg = fmaf(r, hg, xg_own);   // xn + r*hn
            float n = tanh_fast(narg);          // single MUFU on critical tail
            float hnew = n + z * (h_old - n);   // (1-z)n + z h
            sh_h[j] = hnew;
            ys_pending = hnew;                  // STG deferred to next iteration
        }
        __syncthreads();  // h updated & visible before next dot
    }
    if (grp == 2) g_ys[(size_t)(N_NODES - 1) * HID + j] = ys_pending;
    if (tid < HID) hT[tid] = sh_h[tid];
}

// ---------------- K7: readout + output assembly ----------------
__global__ void k_readout(const float* __restrict__ x, const float* __restrict__ Wfc,
                          const float* __restrict__ bfc, float* __restrict__ out) {
    int warp = (blockIdx.x * blockDim.x + threadIdx.x) >> 5;
    int lane = threadIdx.x & 31;
    if (warp >= N_NODES) return;
    const float* y = g_ys + (size_t)warp * HID;
    float y0 = y[lane], y1 = y[lane + 32], y2 = y[lane + 64], y3 = y[lane + 96];
    float o[4];
#pragma unroll
    for (int c = 0; c < 4; c++) {
        float p = y0 * Wfc[lane * 4 + c];
        p = fmaf(y1, Wfc[(lane + 32) * 4 + c], p);
        p = fmaf(y2, Wfc[(lane + 64) * 4 + c], p);
        p = fmaf(y3, Wfc[(lane + 96) * 4 + c], p);
#pragma unroll
        for (int off = 16; off; off >>= 1) p += __shfl_xor_sync(0xffffffffu, p, off);
        o[c] = p;
    }
    float* nx = out + (size_t)warp * 8;
    if (lane < 3) nx[lane] = x[(size_t)warp * IN_DIM + lane];
    if (lane == 3) nx[7] = x[(size_t)warp * IN_DIM + 7];
    if (lane == 4) nx[3] = o[0] + bfc[0];
    if (lane == 5) nx[4] = o[1] + bfc[1];
    if (lane == 6) nx[5] = o[2] + bfc[2];
    if (lane == 7) nx[6] = o[3] + bfc[3];
}

// ---------------- launch ----------------
extern "C" void kernel_launch(void* const* d_in, const int* in_sizes, int n_in,
                              void* d_out, int out_size) {
    const float* x   = (const float*)d_in[0];
    const int*   ei  = (const int*)d_in[1];
    const float* h0  = (const float*)d_in[2];
    const float* Wg  = (const float*)d_in[3];
    const float* bg  = (const float*)d_in[4];
    const float* Wih = (const float*)d_in[5];
    const float* Whh = (const float*)d_in[6];
    const float* bih = (const float*)d_in[7];
    const float* bhh = (const float*)d_in[8];
    const float* Wfc = (const float*)d_in[9];
    const float* bfc = (const float*)d_in[10];
    float* out = (float*)d_out;

    k_init_deg<<<(N_NODES + 255) / 256, 256>>>();
    k_deg<<<(N_EDGES + 255) / 256, 256>>>(ei);
    k_lin<<<N_NODES, HID>>>(x, Wg);
    long long scat_threads = (long long)N_EDGES * (HID / 4);
    k_scatter<<<(int)((scat_threads + 255) / 256), 256>>>(ei);
    k_xg<<<148, G3>>>(Wih, bih, bg);
    k_gru<<<1, G3>>>(Whh, bhh, h0, out + (size_t)N_NODES * 8);
    k_readout<<<(N_NODES + 7) / 8, 256>>>(x, Wfc, bfc, out);
}

// round 15
// speedup vs baseline: 1.2211x; 1.2211x over previous
#include <cuda_runtime.h>
#include <cuda_fp16.h>
#include <cstdint>

#define N_NODES 20000
#define N_EDGES 1280000
#define IN_DIM 16
#define HID 128
#define G3 384
#define OUT_DIM 4

// ---------------- scratch (static device globals; no allocation) ----------------
__device__ float g_deg[N_NODES];
__device__ float g_s[N_NODES * HID];      // (x@W_gcn) * dinv  (messages, pre-scaled)
__device__ float g_agg[N_NODES * HID];    // scatter-add accumulator (init = self term)
__device__ float g_xg[N_NODES * G3];      // precomputed input gates
__device__ float g_ys[N_NODES * HID];     // GRU outputs

// ---------------- packed f32x2 helpers ----------------
__device__ __forceinline__ unsigned long long ffma2(unsigned long long a,
                                                    unsigned long long b,
                                                    unsigned long long c) {
    unsigned long long d;
    asm("fma.rn.f32x2 %0, %1, %2, %3;" : "=l"(d) : "l"(a), "l"(b), "l"(c));
    return d;
}
__device__ __forceinline__ float2 u2f2(unsigned long long u) {
    float2 f;
    asm("mov.b64 {%0, %1}, %2;" : "=f"(f.x), "=f"(f.y) : "l"(u));
    return f;
}
// MUFU.TANH-based activations (measured R8/R9: negligible accumulated error)
__device__ __forceinline__ float tanh_fast(float x) {
    float y;
    asm("tanh.approx.f32 %0, %1;" : "=f"(y) : "f"(x));
    return y;
}
__device__ __forceinline__ float sigmoid_fast_half(float half_x) {
    // sigmoid(x) = 0.5*tanh(x/2)+0.5, caller passes x/2
    return fmaf(tanh_fast(half_x), 0.5f, 0.5f);
}

// ---------------- K1: deg init (self-loop => 1) ----------------
__global__ void k_init_deg() {
    int i = blockIdx.x * blockDim.x + threadIdx.x;
    if (i < N_NODES) g_deg[i] = 1.0f;
}

// ---------------- K2: in-degree over targets ----------------
__global__ void k_deg(const int* __restrict__ ei) {
    int e = blockIdx.x * blockDim.x + threadIdx.x;
    if (e < N_EDGES) atomicAdd(&g_deg[ei[N_EDGES + e]], 1.0f);
}

// ---------------- K3: s = (x @ W_gcn) * dinv ; agg init with self term ----------------
__global__ void k_lin(const float* __restrict__ x, const float* __restrict__ Wg) {
    __shared__ float sx[IN_DIM];
    int node = blockIdx.x;
    int tid = threadIdx.x;  // 128 threads
    if (tid < IN_DIM) sx[tid] = x[node * IN_DIM + tid];
    __syncthreads();
    float acc = 0.0f;
#pragma unroll
    for (int k = 0; k < IN_DIM; k++) acc = fmaf(sx[k], Wg[k * HID + tid], acc);
    float s = acc * rsqrtf(g_deg[node]);
    g_s[(size_t)node * HID + tid] = s;
    g_agg[(size_t)node * HID + tid] = s;  // self-loop contribution (pre outer dinv)
}

// ---------------- K4: scatter-add messages (vector red.v4) ----------------
__global__ void k_scatter(const int* __restrict__ ei) {
    long long gid = (long long)blockIdx.x * blockDim.x + threadIdx.x;
    if (gid >= (long long)N_EDGES * (HID / 4)) return;
    int e = (int)(gid >> 5);          // 32 float4 chunks per edge
    int q = (int)(gid & 31);
    int r = ei[e];
    int c = ei[N_EDGES + e];
    const float4* src = (const float4*)(g_s + (size_t)r * HID) + q;
    float4 v = *src;
    float* dst = g_agg + (size_t)c * HID + 4 * q;
    asm volatile("red.global.v4.f32.add [%0], {%1, %2, %3, %4};"
                 :: "l"(dst), "f"(v.x), "f"(v.y), "f"(v.z), "f"(v.w) : "memory");
}

// ---------------- K5: xg = (agg*dinv + b_gcn) @ W_ih.T + b_ih (fp32) ----------------
__global__ void __launch_bounds__(G3, 1)
k_xg(const float* __restrict__ Wih, const float* __restrict__ bih,
     const float* __restrict__ bgcn) {
    __shared__ __align__(16) float sg[HID];
    int tid = threadIdx.x;
    unsigned long long w[HID / 2];
    const unsigned long long* wr =
        (const unsigned long long*)(Wih + (size_t)tid * HID);
#pragma unroll
    for (int m = 0; m < HID / 2; m++) w[m] = wr[m];
    float b = bih[tid];
    float bg = (tid < HID) ? bgcn[tid] : 0.0f;

    for (int node = blockIdx.x; node < N_NODES; node += gridDim.x) {
        __syncthreads();
        if (tid < HID) {
            float dv = rsqrtf(g_deg[node]);
            sg[tid] = fmaf(g_agg[(size_t)node * HID + tid], dv, bg);
        }
        __syncthreads();
        unsigned long long a0 = 0ull, a1 = 0ull;
        const ulonglong2* hp = (const ulonglong2*)sg;
#pragma unroll
        for (int m = 0; m < HID / 4; m++) {   // 32 entries: full 128 floats
            ulonglong2 hv = hp[m];
            a0 = ffma2(w[2 * m], hv.x, a0);
            a1 = ffma2(w[2 * m + 1], hv.y, a1);
        }
        float2 f0 = u2f2(a0), f1 = u2f2(a1);
        g_xg[(size_t)node * G3 + tid] = f0.x + f0.y + f1.x + f1.y + b;
    }
}

// ---------------- K6: sequential GRU scan — fp16 matvec (HFMA2, rt=2) ----------------
// R9-green protocol (arrive/sync bar1 + trailing __syncthreads), but the
// recurrent matvec runs in fp16: W_hh row converted to 64 half2 regs at init,
// the h broadcast copy mirrored in sh_hh (fp16). The h STATE stays exact fp32
// in sh_h (z*h_old path and hT read fp32); only the dot input is quantized.
// fma-pipe floor: 3 warps x (64 HFMA2 + 7 HADD2) x rt2 = 426 cyc (vs 576).
// Index audit: hp4[i] (uint4, i=0..15) = half2 elements 4i..4i+3 of h;
// pairs with w2[4i..4i+3]; covers h[0..127] exactly once.
__global__ void __launch_bounds__(G3, 1)
k_gru(const float* __restrict__ Whh, const float* __restrict__ bhh,
      const float* __restrict__ h0, float* __restrict__ hT) {
    __shared__ __align__(16) float sh_h[HID];      // exact fp32 h state
    __shared__ __align__(16) __half sh_hh[HID];    // fp16 mirror for the dot
    __shared__ float sh_r[HID];
    __shared__ float sh_z[HID];
    int tid = threadIdx.x;
    int grp = tid >> 7;  // 0,1,2
    int j = tid & 127;

    // convert own W_hh row to fp16: 64 half2 regs
    __half2 w2[HID / 2];
    const float2* wrow = (const float2*)(Whh + (size_t)tid * HID);
#pragma unroll
    for (int m = 0; m < HID / 2; m++) {
        float2 wp = wrow[m];
        w2[m] = __floats2half2_rn(wp.x, wp.y);
    }
    float bh = bhh[tid];

    if (tid < HID) {
        float hv = h0[tid];
        sh_h[tid] = hv;
        sh_hh[tid] = __float2half_rn(hv);
    }
    float xg_cur = g_xg[tid];  // t = 0 prefetch
    float ys_pending = 0.0f;   // grp2: h(t-1) awaiting deferred store
    __syncthreads();

    for (int t = 0; t < N_NODES; t++) {
        // deferred g_ys store for step t-1 (grp2 only; overlaps the dot)
        if (grp == 2 && t > 0) g_ys[(size_t)(t - 1) * HID + j] = ys_pending;

        const uint4* hp4 = (const uint4*)sh_hh;  // 16 entries x 8 halves

        // ---- dot: 64 HFMA2 into 8 half2 accumulators ----
        __half2 a0 = __float2half2_rn(0.0f), a1 = a0, a2 = a0, a3 = a0;
        __half2 a4 = a0, a5 = a0, a6 = a0, a7 = a0;
#pragma unroll
        for (int i = 0; i < 16; i += 2) {
            uint4 q0 = hp4[i];
            uint4 q1 = hp4[i + 1];
            a0 = __hfma2(w2[4 * i + 0], *(__half2*)&q0.x, a0);
            a1 = __hfma2(w2[4 * i + 1], *(__half2*)&q0.y, a1);
            a2 = __hfma2(w2[4 * i + 2], *(__half2*)&q0.z, a2);
            a3 = __hfma2(w2[4 * i + 3], *(__half2*)&q0.w, a3);
            a4 = __hfma2(w2[4 * i + 4], *(__half2*)&q1.x, a4);
            a5 = __hfma2(w2[4 * i + 5], *(__half2*)&q1.y, a5);
            a6 = __hfma2(w2[4 * i + 6], *(__half2*)&q1.z, a6);
            a7 = __hfma2(w2[4 * i + 7], *(__half2*)&q1.w, a7);
        }
        // half2 reduction tree, then one conversion to f32
        __half2 t0 = __hadd2(a0, a1), t1 = __hadd2(a2, a3);
        __half2 t2 = __hadd2(a4, a5), t3 = __hadd2(a6, a7);
        __half2 u0 = __hadd2(t0, t1), u1 = __hadd2(t2, t3);
        float2 fsum = __half22float2(__hadd2(u0, u1));
        float hg = fsum.x + fsum.y + bh;   // = W.h + b (fp16 matvec, f32 finish)

        float xg_own = xg_cur;
        int tn = (t + 1 < N_NODES) ? (t + 1) : (N_NODES - 1);  // branch-free clamp
        xg_cur = g_xg[(size_t)tn * G3 + tid];
        float g_sum = hg + xg_own;

        if (grp == 0) {
            sh_r[j] = sigmoid_fast_half(0.5f * g_sum);
            asm volatile("bar.arrive 1, %0;" :: "n"(G3) : "memory");
        } else if (grp == 1) {
            sh_z[j] = sigmoid_fast_half(0.5f * g_sum);
            asm volatile("bar.arrive 1, %0;" :: "n"(G3) : "memory");
        } else {
            float h_old = sh_h[j];  // exact fp32 state
            asm volatile("bar.sync 1, %0;" :: "n"(G3) : "memory");
            float r = sh_r[j];
            float z = sh_z[j];
            float narg = fmaf(r, hg, xg_own);   // xn + r*hn
            float n = tanh_fast(narg);
            float hnew = n + z * (h_old - n);   // (1-z)n + z h
            sh_h[j] = hnew;                     // fp32 state
            sh_hh[j] = __float2half_rn(hnew);   // fp16 mirror for next dot
            ys_pending = hnew;
        }
        __syncthreads();  // h (both copies) visible before next dot
    }
    if (grp == 2) g_ys[(size_t)(N_NODES - 1) * HID + j] = ys_pending;
    if (tid < HID) hT[tid] = sh_h[tid];
}

// ---------------- K7: readout + output assembly ----------------
__global__ void k_readout(const float* __restrict__ x, const float* __restrict__ Wfc,
                          const float* __restrict__ bfc, float* __restrict__ out) {
    int warp = (blockIdx.x * blockDim.x + threadIdx.x) >> 5;
    int lane = threadIdx.x & 31;
    if (warp >= N_NODES) return;
    const float* y = g_ys + (size_t)warp * HID;
    float y0 = y[lane], y1 = y[lane + 32], y2 = y[lane + 64], y3 = y[lane + 96];
    float o[4];
#pragma unroll
    for (int c = 0; c < 4; c++) {
        float p = y0 * Wfc[lane * 4 + c];
        p = fmaf(y1, Wfc[(lane + 32) * 4 + c], p);
        p = fmaf(y2, Wfc[(lane + 64) * 4 + c], p);
        p = fmaf(y3, Wfc[(lane + 96) * 4 + c], p);
#pragma unroll
        for (int off = 16; off; off >>= 1) p += __shfl_xor_sync(0xffffffffu, p, off);
        o[c] = p;
    }
    float* nx = out + (size_t)warp * 8;
    if (lane < 3) nx[lane] = x[(size_t)warp * IN_DIM + lane];
    if (lane == 3) nx[7] = x[(size_t)warp * IN_DIM + 7];
    if (lane == 4) nx[3] = o[0] + bfc[0];
    if (lane == 5) nx[4] = o[1] + bfc[1];
    if (lane == 6) nx[5] = o[2] + bfc[2];
    if (lane == 7) nx[6] = o[3] + bfc[3];
}

// ---------------- launch ----------------
extern "C" void kernel_launch(void* const* d_in, const int* in_sizes, int n_in,
                              void* d_out, int out_size) {
    const float* x   = (const float*)d_in[0];
    const int*   ei  = (const int*)d_in[1];
    const float* h0  = (const float*)d_in[2];
    const float* Wg  = (const float*)d_in[3];
    const float* bg  = (const float*)d_in[4];
    const float* Wih = (const float*)d_in[5];
    const float* Whh = (const float*)d_in[6];
    const float* bih = (const float*)d_in[7];
    const float* bhh = (const float*)d_in[8];
    const float* Wfc = (const float*)d_in[9];
    const float* bfc = (const float*)d_in[10];
    float* out = (float*)d_out;

    k_init_deg<<<(N_NODES + 255) / 256, 256>>>();
    k_deg<<<(N_EDGES + 255) / 256, 256>>>(ei);
    k_lin<<<N_NODES, HID>>>(x, Wg);
    long long scat_threads = (long long)N_EDGES * (HID / 4);
    k_scatter<<<(int)((scat_threads + 255) / 256), 256>>>(ei);
    k_xg<<<148, G3>>>(Wih, bih, bg);
    k_gru<<<1, G3>>>(Whh, bhh, h0, out + (size_t)N_NODES * 8);
    k_readout<<<(N_NODES + 7) / 8, 256>>>(x, Wfc, bfc, out);
}

// round 16
// speedup vs baseline: 1.2813x; 1.0493x over previous
#include <cuda_runtime.h>
#include <cuda_fp16.h>
#include <cstdint>

#define N_NODES 20000
#define N_EDGES 1280000
#define IN_DIM 16
#define HID 128
#define G3 384
#define OUT_DIM 4

// ---------------- scratch (static device globals; no allocation) ----------------
__device__ float g_deg[N_NODES];
__device__ float g_s[N_NODES * HID];      // (x@W_gcn) * dinv  (messages, pre-scaled)
__device__ float g_agg[N_NODES * HID];    // scatter-add accumulator (init = self term)
__device__ float g_xg[N_NODES * G3];      // precomputed input gates
__device__ float g_ys[N_NODES * HID];     // GRU outputs

// ---------------- packed f32x2 helpers ----------------
__device__ __forceinline__ unsigned long long ffma2(unsigned long long a,
                                                    unsigned long long b,
                                                    unsigned long long c) {
    unsigned long long d;
    asm("fma.rn.f32x2 %0, %1, %2, %3;" : "=l"(d) : "l"(a), "l"(b), "l"(c));
    return d;
}
__device__ __forceinline__ float2 u2f2(unsigned long long u) {
    float2 f;
    asm("mov.b64 {%0, %1}, %2;" : "=f"(f.x), "=f"(f.y) : "l"(u));
    return f;
}
// MUFU.TANH-based activations (measured R8/R9: negligible accumulated error)
__device__ __forceinline__ float tanh_fast(float x) {
    float y;
    asm("tanh.approx.f32 %0, %1;" : "=f"(y) : "f"(x));
    return y;
}
__device__ __forceinline__ float sigmoid_fast_half(float half_x) {
    // sigmoid(x) = 0.5*tanh(x/2)+0.5, caller passes x/2
    return fmaf(tanh_fast(half_x), 0.5f, 0.5f);
}

// ---------------- K1: deg init (self-loop => 1) ----------------
__global__ void k_init_deg() {
    int i = blockIdx.x * blockDim.x + threadIdx.x;
    if (i < N_NODES) g_deg[i] = 1.0f;
}

// ---------------- K2: in-degree over targets ----------------
__global__ void k_deg(const int* __restrict__ ei) {
    int e = blockIdx.x * blockDim.x + threadIdx.x;
    if (e < N_EDGES) atomicAdd(&g_deg[ei[N_EDGES + e]], 1.0f);
}

// ---------------- K3: s = (x @ W_gcn) * dinv ; agg init with self term ----------------
__global__ void k_lin(const float* __restrict__ x, const float* __restrict__ Wg) {
    __shared__ float sx[IN_DIM];
    int node = blockIdx.x;
    int tid = threadIdx.x;  // 128 threads
    if (tid < IN_DIM) sx[tid] = x[node * IN_DIM + tid];
    __syncthreads();
    float acc = 0.0f;
#pragma unroll
    for (int k = 0; k < IN_DIM; k++) acc = fmaf(sx[k], Wg[k * HID + tid], acc);
    float s = acc * rsqrtf(g_deg[node]);
    g_s[(size_t)node * HID + tid] = s;
    g_agg[(size_t)node * HID + tid] = s;  // self-loop contribution (pre outer dinv)
}

// ---------------- K4: scatter-add messages (vector red.v4) ----------------
__global__ void k_scatter(const int* __restrict__ ei) {
    long long gid = (long long)blockIdx.x * blockDim.x + threadIdx.x;
    if (gid >= (long long)N_EDGES * (HID / 4)) return;
    int e = (int)(gid >> 5);          // 32 float4 chunks per edge
    int q = (int)(gid & 31);
    int r = ei[e];
    int c = ei[N_EDGES + e];
    const float4* src = (const float4*)(g_s + (size_t)r * HID) + q;
    float4 v = *src;
    float* dst = g_agg + (size_t)c * HID + 4 * q;
    asm volatile("red.global.v4.f32.add [%0], {%1, %2, %3, %4};"
                 :: "l"(dst), "f"(v.x), "f"(v.y), "f"(v.z), "f"(v.w) : "memory");
}

// ---------------- K5: xg = (agg*dinv + b_gcn) @ W_ih.T + b_ih (fp32) ----------------
__global__ void __launch_bounds__(G3, 1)
k_xg(const float* __restrict__ Wih, const float* __restrict__ bih,
     const float* __restrict__ bgcn) {
    __shared__ __align__(16) float sg[HID];
    int tid = threadIdx.x;
    unsigned long long w[HID / 2];
    const unsigned long long* wr =
        (const unsigned long long*)(Wih + (size_t)tid * HID);
#pragma unroll
    for (int m = 0; m < HID / 2; m++) w[m] = wr[m];
    float b = bih[tid];
    float bg = (tid < HID) ? bgcn[tid] : 0.0f;

    for (int node = blockIdx.x; node < N_NODES; node += gridDim.x) {
        __syncthreads();
        if (tid < HID) {
            float dv = rsqrtf(g_deg[node]);
            sg[tid] = fmaf(g_agg[(size_t)node * HID + tid], dv, bg);
        }
        __syncthreads();
        unsigned long long a0 = 0ull, a1 = 0ull;
        const ulonglong2* hp = (const ulonglong2*)sg;
#pragma unroll
        for (int m = 0; m < HID / 4; m++) {   // 32 entries: full 128 floats
            ulonglong2 hv = hp[m];
            a0 = ffma2(w[2 * m], hv.x, a0);
            a1 = ffma2(w[2 * m + 1], hv.y, a1);
        }
        float2 f0 = u2f2(a0), f1 = u2f2(a1);
        g_xg[(size_t)node * G3 + tid] = f0.x + f0.y + f1.x + f1.y + b;
    }
}

// ---------------- K6: sequential GRU scan — fp16 matvec + arbiter-aware groups ----
// R15-green fp16 HFMA2 dot. Single delta: group->warp remap to exploit the
// hi-wid-first arbiter. n-group (the bar.sync CONSUMER) now sits in warps 0-3
// (lowest priority); r (warps 4-7) and z (warps 8-11) producers get issue
// priority, publish sigmoids + arrive earlier; n warps reach bar.sync last
// and take the released fast path.
//   sec = tid>>7: 0 -> n-rows (gidx 2H+j), 1 -> r-rows (j), 2 -> z-rows (H+j)
__global__ void __launch_bounds__(G3, 1)
k_gru(const float* __restrict__ Whh, const float* __restrict__ bhh,
      const float* __restrict__ h0, float* __restrict__ hT) {
    __shared__ __align__(16) float sh_h[HID];      // exact fp32 h state
    __shared__ __align__(16) __half sh_hh[HID];    // fp16 mirror for the dot
    __shared__ float sh_r[HID];
    __shared__ float sh_z[HID];
    int tid = threadIdx.x;
    int sec = tid >> 7;  // 0: n (consumer, low-wid), 1: r, 2: z (producers)
    int j = tid & 127;
    int grow = (sec == 0) ? (2 * HID + j) : ((sec == 1) ? j : (HID + j));

    // convert own W_hh row to fp16: 64 half2 regs
    __half2 w2[HID / 2];
    const float2* wrow = (const float2*)(Whh + (size_t)grow * HID);
#pragma unroll
    for (int m = 0; m < HID / 2; m++) {
        float2 wp = wrow[m];
        w2[m] = __floats2half2_rn(wp.x, wp.y);
    }
    float bh = bhh[grow];

    if (tid < HID) {
        float hv = h0[tid];
        sh_h[tid] = hv;
        sh_hh[tid] = __float2half_rn(hv);
    }
    float xg_cur = g_xg[grow];  // t = 0 prefetch
    float ys_pending = 0.0f;    // n-group: h(t-1) awaiting deferred store
    __syncthreads();

    for (int t = 0; t < N_NODES; t++) {
        // deferred g_ys store for step t-1 (n-group only; overlaps the dot)
        if (sec == 0 && t > 0) g_ys[(size_t)(t - 1) * HID + j] = ys_pending;

        const uint4* hp4 = (const uint4*)sh_hh;  // 16 entries x 8 halves

        // ---- dot: 64 HFMA2 into 8 half2 accumulators ----
        __half2 a0 = __float2half2_rn(0.0f), a1 = a0, a2 = a0, a3 = a0;
        __half2 a4 = a0, a5 = a0, a6 = a0, a7 = a0;
#pragma unroll
        for (int i = 0; i < 16; i += 2) {
            uint4 q0 = hp4[i];
            uint4 q1 = hp4[i + 1];
            a0 = __hfma2(w2[4 * i + 0], *(__half2*)&q0.x, a0);
            a1 = __hfma2(w2[4 * i + 1], *(__half2*)&q0.y, a1);
            a2 = __hfma2(w2[4 * i + 2], *(__half2*)&q0.z, a2);
            a3 = __hfma2(w2[4 * i + 3], *(__half2*)&q0.w, a3);
            a4 = __hfma2(w2[4 * i + 4], *(__half2*)&q1.x, a4);
            a5 = __hfma2(w2[4 * i + 5], *(__half2*)&q1.y, a5);
            a6 = __hfma2(w2[4 * i + 6], *(__half2*)&q1.z, a6);
            a7 = __hfma2(w2[4 * i + 7], *(__half2*)&q1.w, a7);
        }
        // half2 reduction tree, then one conversion to f32
        __half2 t0 = __hadd2(a0, a1), t1 = __hadd2(a2, a3);
        __half2 t2 = __hadd2(a4, a5), t3 = __hadd2(a6, a7);
        __half2 u0 = __hadd2(t0, t1), u1 = __hadd2(t2, t3);
        float2 fsum = __half22float2(__hadd2(u0, u1));
        float hg = fsum.x + fsum.y + bh;   // = W.h + b (fp16 matvec, f32 finish)

        float xg_own = xg_cur;
        int tn = (t + 1 < N_NODES) ? (t + 1) : (N_NODES - 1);  // branch-free clamp
        xg_cur = g_xg[(size_t)tn * G3 + grow];
        float g_sum = hg + xg_own;

        if (sec == 1) {
            sh_r[j] = sigmoid_fast_half(0.5f * g_sum);
            asm volatile("bar.arrive 1, %0;" :: "n"(G3) : "memory");
        } else if (sec == 2) {
            sh_z[j] = sigmoid_fast_half(0.5f * g_sum);
            asm volatile("bar.arrive 1, %0;" :: "n"(G3) : "memory");
        } else {
            float h_old = sh_h[j];  // exact fp32 state, own-thread slot
            asm volatile("bar.sync 1, %0;" :: "n"(G3) : "memory");
            float r = sh_r[j];
            float z = sh_z[j];
            float narg = fmaf(r, hg, xg_own);   // xn + r*hn
            float n = tanh_fast(narg);
            float hnew = n + z * (h_old - n);   // (1-z)n + z h
            sh_h[j] = hnew;                     // fp32 state
            sh_hh[j] = __float2half_rn(hnew);   // fp16 mirror for next dot
            ys_pending = hnew;
        }
        __syncthreads();  // h (both copies) visible before next dot
    }
    if (sec == 0) g_ys[(size_t)(N_NODES - 1) * HID + j] = ys_pending;
    if (tid < HID) hT[tid] = sh_h[tid];
}

// ---------------- K7: readout + output assembly ----------------
__global__ void k_readout(const float* __restrict__ x, const float* __restrict__ Wfc,
                          const float* __restrict__ bfc, float* __restrict__ out) {
    int warp = (blockIdx.x * blockDim.x + threadIdx.x) >> 5;
    int lane = threadIdx.x & 31;
    if (warp >= N_NODES) return;
    const float* y = g_ys + (size_t)warp * HID;
    float y0 = y[lane], y1 = y[lane + 32], y2 = y[lane + 64], y3 = y[lane + 96];
    float o[4];
#pragma unroll
    for (int c = 0; c < 4; c++) {
        float p = y0 * Wfc[lane * 4 + c];
        p = fmaf(y1, Wfc[(lane + 32) * 4 + c], p);
        p = fmaf(y2, Wfc[(lane + 64) * 4 + c], p);
        p = fmaf(y3, Wfc[(lane + 96) * 4 + c], p);
#pragma unroll
        for (int off = 16; off; off >>= 1) p += __shfl_xor_sync(0xffffffffu, p, off);
        o[c] = p;
    }
    float* nx = out + (size_t)warp * 8;
    if (lane < 3) nx[lane] = x[(size_t)warp * IN_DIM + lane];
    if (lane == 3) nx[7] = x[(size_t)warp * IN_DIM + 7];
    if (lane == 4) nx[3] = o[0] + bfc[0];
    if (lane == 5) nx[4] = o[1] + bfc[1];
    if (lane == 6) nx[5] = o[2] + bfc[2];
    if (lane == 7) nx[6] = o[3] + bfc[3];
}

// ---------------- launch ----------------
extern "C" void kernel_launch(void* const* d_in, const int* in_sizes, int n_in,
                              void* d_out, int out_size) {
    const float* x   = (const float*)d_in[0];
    const int*   ei  = (const int*)d_in[1];
    const float* h0  = (const float*)d_in[2];
    const float* Wg  = (const float*)d_in[3];
    const float* bg  = (const float*)d_in[4];
    const float* Wih = (const float*)d_in[5];
    const float* Whh = (const float*)d_in[6];
    const float* bih = (const float*)d_in[7];
    const float* bhh = (const float*)d_in[8];
    const float* Wfc = (const float*)d_in[9];
    const float* bfc = (const float*)d_in[10];
    float* out = (float*)d_out;

    k_init_deg<<<(N_NODES + 255) / 256, 256>>>();
    k_deg<<<(N_EDGES + 255) / 256, 256>>>(ei);
    k_lin<<<N_NODES, HID>>>(x, Wg);
    long long scat_threads = (long long)N_EDGES * (HID / 4);
    k_scatter<<<(int)((scat_threads + 255) / 256), 256>>>(ei);
    k_xg<<<148, G3>>>(Wih, bih, bg);
    k_gru<<<1, G3>>>(Whh, bhh, h0, out + (size_t)N_NODES * 8);
    k_readout<<<(N_NODES + 7) / 8, 256>>>(x, Wfc, bfc, out);
}